// round 1
// baseline (speedup 1.0000x reference)
#include <cuda_runtime.h>
#include <math.h>
#include <stdint.h>

// ---------------- problem constants ----------------
#define T_DIM 2048
#define H_DIM 2048
#define NHEAD 16
#define HD    128
#define NE    16
#define KTOP  2
#define FF    1024
#define SF    4096
#define TK    (T_DIM * KTOP)

// ---------------- scratch (device globals; no allocations allowed) --------
__device__ float g_h   [T_DIM * H_DIM];
__device__ float g_qkv [T_DIM * 3 * H_DIM];
__device__ float g_ctx [T_DIM * H_DIM];
__device__ float g_x1  [T_DIM * H_DIM];
__device__ float g_h2  [T_DIM * H_DIM];
__device__ float g_sg  [T_DIM * 2 * SF];      // shared ffn gate|up
__device__ float g_mid [T_DIM * SF];          // shared ffn activated
__device__ float g_sho [T_DIM * H_DIM];       // shared ffn out
__device__ float g_gu  [TK * 2 * FF];         // moe gate|up per routed slot
__device__ float g_act [TK * FF];             // moe activated
__device__ float g_slot[KTOP * T_DIM * H_DIM];// moe contribution per slot
__device__ int   g_topi[TK];
__device__ float g_topw[TK];
__device__ int   g_cnt[NE];
__device__ int   g_off[NE];
__device__ int   g_cur[NE];
__device__ int   g_perm[TK];                  // grouped position -> (t*2+k)

// ---------------- rmsnorm ----------------
__global__ __launch_bounds__(256) void rmsnorm_kernel(
    const float* __restrict__ x, const float* __restrict__ g, float* __restrict__ o)
{
    int row = blockIdx.x;
    int tid = threadIdx.x;
    const float4* xr = reinterpret_cast<const float4*>(x + (size_t)row * H_DIM);
    const float4* gr = reinterpret_cast<const float4*>(g);
    float4* orow = reinterpret_cast<float4*>(o + (size_t)row * H_DIM);

    float4 a = xr[tid];
    float4 b = xr[tid + 256];
    float ss = a.x*a.x + a.y*a.y + a.z*a.z + a.w*a.w
             + b.x*b.x + b.y*b.y + b.z*b.z + b.w*b.w;
    #pragma unroll
    for (int off = 16; off; off >>= 1) ss += __shfl_xor_sync(0xffffffffu, ss, off);
    __shared__ float red[8];
    if ((tid & 31) == 0) red[tid >> 5] = ss;
    __syncthreads();
    float tot = 0.f;
    #pragma unroll
    for (int i = 0; i < 8; i++) tot += red[i];
    float inv = rsqrtf(tot * (1.0f / H_DIM) + 1e-6f);
    float4 ga = gr[tid], gb = gr[tid + 256];
    float4 oa, ob;
    oa.x = a.x*inv*ga.x; oa.y = a.y*inv*ga.y; oa.z = a.z*inv*ga.z; oa.w = a.w*inv*ga.w;
    ob.x = b.x*inv*gb.x; ob.y = b.y*inv*gb.y; ob.z = b.z*inv*gb.z; ob.w = b.w*inv*gb.w;
    orow[tid] = oa;
    orow[tid + 256] = ob;
}

// ---------------- classic 128x128x8 SGEMM (A[M,K] * B[K,N]) ----------------
#define BM 128
#define BN 128
#define BKD 8

template<int EPI>  // 0: C=acc   1: C=acc+R
__global__ __launch_bounds__(256) void sgemm_kernel(
    const float* __restrict__ A, const float* __restrict__ B,
    float* __restrict__ C, const float* __restrict__ R,
    int M, int N, int K)
{
    __shared__ float As[BKD][BM];
    __shared__ float Bs[BKD][BN];
    int tid = threadIdx.x;
    int bm = blockIdx.y * BM, bn = blockIdx.x * BN;
    int aRow = tid >> 1, aCol = (tid & 1) << 2;
    int bRow = tid >> 5, bCol = (tid & 31) << 2;
    int tx = tid & 15, ty = tid >> 4;

    bool aValid = (bm + aRow) < M;
    const float* aPtr = A + (size_t)(bm + aRow) * K + aCol;
    const float* bPtr = B + (size_t)bRow * N + bn + bCol;

    float4 aReg = aValid ? *(const float4*)aPtr : make_float4(0,0,0,0);
    float4 bReg = *(const float4*)bPtr;
    float acc[8][8] = {};
    int nk = K / BKD;
    for (int kt = 0; kt < nk; ++kt) {
        As[aCol+0][aRow] = aReg.x; As[aCol+1][aRow] = aReg.y;
        As[aCol+2][aRow] = aReg.z; As[aCol+3][aRow] = aReg.w;
        *(float4*)&Bs[bRow][bCol] = bReg;
        __syncthreads();
        if (kt + 1 < nk) {
            aReg = aValid ? *(const float4*)(aPtr + (size_t)(kt+1)*BKD) : make_float4(0,0,0,0);
            bReg = *(const float4*)(bPtr + (size_t)(kt+1)*BKD*N);
        }
        #pragma unroll
        for (int kk = 0; kk < BKD; ++kk) {
            float a[8], b[8];
            *(float4*)(a)   = *(const float4*)&As[kk][ty*8];
            *(float4*)(a+4) = *(const float4*)&As[kk][ty*8+4];
            *(float4*)(b)   = *(const float4*)&Bs[kk][tx*8];
            *(float4*)(b+4) = *(const float4*)&Bs[kk][tx*8+4];
            #pragma unroll
            for (int i = 0; i < 8; i++)
                #pragma unroll
                for (int j = 0; j < 8; j++)
                    acc[i][j] += a[i] * b[j];
        }
        __syncthreads();
    }
    #pragma unroll
    for (int i = 0; i < 8; i++) {
        int row = bm + ty*8 + i;
        if (row >= M) continue;
        float* cp = C + (size_t)row * N + bn + tx*8;
        if (EPI == 1) {
            const float* rp = R + (size_t)row * N + bn + tx*8;
            #pragma unroll
            for (int j = 0; j < 8; j++) acc[i][j] += rp[j];
        }
        *(float4*)(cp)   = *(float4*)&acc[i][0];
        *(float4*)(cp+4) = *(float4*)&acc[i][4];
    }
}

// ---------------- RoPE (in-place on q,k inside g_qkv) ----------------
__global__ void rope_kernel()
{
    int idx = blockIdx.x * blockDim.x + threadIdx.x;
    if (idx >= T_DIM * NHEAD * (HD/2)) return;
    int d = idx & 63;
    int h = (idx >> 6) & 15;
    int t = idx >> 10;
    float freq = powf(10000.0f, -(float)d * (1.0f/64.0f));
    float ang = (float)t * freq;
    float s, c;
    sincosf(ang, &s, &c);
    float* q = g_qkv + (size_t)t * (3*H_DIM) + h * HD + d;
    float q1 = q[0], q2 = q[64];
    q[0]  = q1*c - q2*s;
    q[64] = q1*s + q2*c;
    float* k = q + H_DIM;
    float k1 = k[0], k2 = k[64];
    k[0]  = k1*c - k2*s;
    k[64] = k1*s + k2*c;
}

// ---------------- causal flash attention (fp32) ----------------
// grid: (T/64, NHEAD), 256 threads, dynamic smem
#define FL_SMEM_FLOATS (64*128 + 64*129 + 64*128 + 64*65 + 64 + 64)
__global__ __launch_bounds__(256) void flash_kernel()
{
    extern __shared__ float sm[];
    float* Qs = sm;              // [64][128]
    float* Ks = Qs + 64*128;     // [64][129] (pad: conflict-free lane reads)
    float* Vs = Ks + 64*129;     // [64][128]
    float* Ss = Vs + 64*128;     // [64][65]
    float* Al = Ss + 64*65;      // [64]
    float* Lf = Al + 64;         // [64]

    int qt = blockIdx.x, head = blockIdx.y;
    int tid = threadIdx.x, lane = tid & 31, warp = tid >> 5;
    const float scale = 0.08838834764831845f; // 1/sqrt(128)

    // load Q tile (pre-scaled)
    for (int it = tid; it < 64*32; it += 256) {
        int r = it >> 5, cs = (it & 31) << 2;
        float4 v = *(const float4*)(g_qkv + (size_t)(qt*64 + r)*(3*H_DIM) + head*HD + cs);
        float* qp = Qs + r*128 + cs;
        qp[0]=v.x*scale; qp[1]=v.y*scale; qp[2]=v.z*scale; qp[3]=v.w*scale;
    }

    float m_r = -1e30f, l_r = 0.f;
    float o0[16], o1[16];
    #pragma unroll
    for (int j = 0; j < 16; j++) { o0[j] = 0.f; o1[j] = 0.f; }
    int rr0 = lane, rr1 = lane + 32, db = warp * 16;

    for (int kt = 0; kt <= qt; ++kt) {
        // load K, V tiles
        for (int it = tid; it < 64*32; it += 256) {
            int r = it >> 5, cs = (it & 31) << 2;
            const float* kp = g_qkv + (size_t)(kt*64 + r)*(3*H_DIM) + H_DIM + head*HD + cs;
            float4 kv = *(const float4*)kp;
            float* kd = Ks + r*129 + cs;
            kd[0]=kv.x; kd[1]=kv.y; kd[2]=kv.z; kd[3]=kv.w;
            *(float4*)(Vs + r*128 + cs) = *(const float4*)(kp + H_DIM);
        }
        __syncthreads();

        // S = Q K^T  (warp owns rows warp*8..+7, lane owns cols lane & lane+32)
        float acc[8][2];
        #pragma unroll
        for (int i = 0; i < 8; i++) { acc[i][0] = 0.f; acc[i][1] = 0.f; }
        const float* k0p = Ks + lane*129;
        const float* k1p = Ks + (lane+32)*129;
        const float* q0p = Qs + (warp*8)*128;
        #pragma unroll 4
        for (int d = 0; d < 128; ++d) {
            float k0 = k0p[d], k1 = k1p[d];
            #pragma unroll
            for (int i = 0; i < 8; i++) {
                float q = q0p[i*128 + d];
                acc[i][0] += q * k0;
                acc[i][1] += q * k1;
            }
        }
        bool diag = (kt == qt);
        #pragma unroll
        for (int i = 0; i < 8; i++) {
            int r = warp*8 + i;
            float s0 = acc[i][0], s1 = acc[i][1];
            if (diag) {
                if (lane > r)      s0 = -1e30f;
                if (lane + 32 > r) s1 = -1e30f;
            }
            Ss[r*65 + lane]      = s0;
            Ss[r*65 + lane + 32] = s1;
        }
        __syncthreads();

        // per-row online softmax stats (threads 0..63 own rows)
        if (tid < 64) {
            float* srow = Ss + tid*65;
            float mx = m_r;
            #pragma unroll 8
            for (int c = 0; c < 64; c++) mx = fmaxf(mx, srow[c]);
            float al = __expf(m_r - mx);
            float sum = 0.f;
            #pragma unroll 4
            for (int c = 0; c < 64; c++) {
                float p = __expf(srow[c] - mx);
                srow[c] = p;
                sum += p;
            }
            l_r = l_r * al + sum;
            m_r = mx;
            Al[tid] = al;
        }
        __syncthreads();

        // O = O*alpha + P V  (thread owns rows {lane, lane+32}, dims [db, db+16))
        float a0 = Al[rr0], a1 = Al[rr1];
        #pragma unroll
        for (int j = 0; j < 16; j++) { o0[j] *= a0; o1[j] *= a1; }
        #pragma unroll 2
        for (int c = 0; c < 64; c++) {
            float p0 = Ss[rr0*65 + c], p1 = Ss[rr1*65 + c];
            const float* vp = Vs + c*128 + db;
            #pragma unroll
            for (int j = 0; j < 16; j++) {
                float v = vp[j];
                o0[j] += p0 * v;
                o1[j] += p1 * v;
            }
        }
        __syncthreads();
    }

    if (tid < 64) Lf[tid] = l_r;
    __syncthreads();
    float inv0 = 1.f / Lf[rr0], inv1 = 1.f / Lf[rr1];
    float* c0 = g_ctx + (size_t)(qt*64 + rr0) * H_DIM + head*HD + db;
    float* c1 = g_ctx + (size_t)(qt*64 + rr1) * H_DIM + head*HD + db;
    #pragma unroll
    for (int j = 0; j < 16; j++) { c0[j] = o0[j]*inv0; c1[j] = o1[j]*inv1; }
}

// ---------------- router: logits + softmax-top2 (1 warp / token) --------
__global__ __launch_bounds__(256) void router_kernel(const float* __restrict__ gate_w)
{
    int gwarp = (blockIdx.x * blockDim.x + threadIdx.x) >> 5;
    int lane = threadIdx.x & 31;
    if (gwarp >= T_DIM) return;
    const float* hrow = g_h2 + (size_t)gwarp * H_DIM;
    float acc[NE];
    #pragma unroll
    for (int e = 0; e < NE; e++) acc[e] = 0.f;
    for (int i = lane; i < H_DIM; i += 32) {
        float hv = hrow[i];
        const float4* gw = reinterpret_cast<const float4*>(gate_w + (size_t)i * NE);
        #pragma unroll
        for (int q = 0; q < 4; q++) {
            float4 g4 = gw[q];
            acc[q*4+0] += hv * g4.x;
            acc[q*4+1] += hv * g4.y;
            acc[q*4+2] += hv * g4.z;
            acc[q*4+3] += hv * g4.w;
        }
    }
    #pragma unroll
    for (int e = 0; e < NE; e++)
        #pragma unroll
        for (int off = 16; off; off >>= 1)
            acc[e] += __shfl_xor_sync(0xffffffffu, acc[e], off);
    if (lane == 0) {
        float best = -1e30f; int bi = 0;
        #pragma unroll
        for (int e = 0; e < NE; e++) if (acc[e] > best) { best = acc[e]; bi = e; }
        float best2 = -1e30f; int bi2 = 0;
        #pragma unroll
        for (int e = 0; e < NE; e++) if (e != bi && acc[e] > best2) { best2 = acc[e]; bi2 = e; }
        float e1 = expf(best2 - best);           // best >= best2
        float w0 = 1.f / (1.f + e1);
        float w1 = e1 / (1.f + e1);
        g_topi[2*gwarp]   = bi;  g_topw[2*gwarp]   = w0;
        g_topi[2*gwarp+1] = bi2; g_topw[2*gwarp+1] = w1;
    }
}

// ---------------- expert grouping ----------------
__global__ void zero_cnt_kernel() {
    int i = threadIdx.x;
    if (i < NE) { g_cnt[i] = 0; g_cur[i] = 0; }
}
__global__ void count_kernel() {
    int i = blockIdx.x * blockDim.x + threadIdx.x;
    if (i < TK) atomicAdd(&g_cnt[g_topi[i]], 1);
}
__global__ void scan_kernel() {
    if (threadIdx.x == 0) {
        int o = 0;
        for (int e = 0; e < NE; e++) { g_off[e] = o; g_cur[e] = o; o += g_cnt[e]; }
    }
}
__global__ void scatter_kernel() {
    int i = blockIdx.x * blockDim.x + threadIdx.x;
    if (i < TK) {
        int e = g_topi[i];
        int p = atomicAdd(&g_cur[e], 1);
        g_perm[p] = i;
    }
}

// ---------------- grouped MoE up GEMM: gathered h2 rows @ moe_up[e] ------
__global__ __launch_bounds__(256) void moe_up_kernel(const float* __restrict__ moe_up_w)
{
    int e = blockIdx.z;
    int cnt = g_cnt[e];
    int bm = blockIdx.y * BM;
    if (bm >= cnt) return;
    int off = g_off[e];
    const float* B = moe_up_w + (size_t)e * H_DIM * (2*FF);
    const int N = 2*FF, K = H_DIM;
    int bn = blockIdx.x * BN;

    __shared__ float As[BKD][BM];
    __shared__ float Bs[BKD][BN];
    int tid = threadIdx.x;
    int aRow = tid >> 1, aCol = (tid & 1) << 2;
    int bRow = tid >> 5, bCol = (tid & 31) << 2;
    int tx = tid & 15, ty = tid >> 4;

    int lr = bm + aRow;
    bool aValid = lr < cnt;
    const float* aPtr = nullptr;
    if (aValid) {
        int t = g_perm[off + lr] >> 1;
        aPtr = g_h2 + (size_t)t * H_DIM + aCol;
    }
    const float* bPtr = B + (size_t)bRow * N + bn + bCol;

    float4 aReg = aValid ? *(const float4*)aPtr : make_float4(0,0,0,0);
    float4 bReg = *(const float4*)bPtr;
    float acc[8][8] = {};
    int nk = K / BKD;
    for (int kt = 0; kt < nk; ++kt) {
        As[aCol+0][aRow] = aReg.x; As[aCol+1][aRow] = aReg.y;
        As[aCol+2][aRow] = aReg.z; As[aCol+3][aRow] = aReg.w;
        *(float4*)&Bs[bRow][bCol] = bReg;
        __syncthreads();
        if (kt + 1 < nk) {
            aReg = aValid ? *(const float4*)(aPtr + (size_t)(kt+1)*BKD) : make_float4(0,0,0,0);
            bReg = *(const float4*)(bPtr + (size_t)(kt+1)*BKD*N);
        }
        #pragma unroll
        for (int kk = 0; kk < BKD; ++kk) {
            float a[8], b[8];
            *(float4*)(a)   = *(const float4*)&As[kk][ty*8];
            *(float4*)(a+4) = *(const float4*)&As[kk][ty*8+4];
            *(float4*)(b)   = *(const float4*)&Bs[kk][tx*8];
            *(float4*)(b+4) = *(const float4*)&Bs[kk][tx*8+4];
            #pragma unroll
            for (int i = 0; i < 8; i++)
                #pragma unroll
                for (int j = 0; j < 8; j++)
                    acc[i][j] += a[i] * b[j];
        }
        __syncthreads();
    }
    #pragma unroll
    for (int i = 0; i < 8; i++) {
        int lrow = bm + ty*8 + i;
        if (lrow >= cnt) continue;
        float* cp = g_gu + (size_t)(off + lrow) * (2*FF) + bn + tx*8;
        *(float4*)(cp)   = *(float4*)&acc[i][0];
        *(float4*)(cp+4) = *(float4*)&acc[i][4];
    }
}

// ---------------- moe activation: act = silu(g)*u ----------------
__global__ void moe_act_kernel()
{
    int idx = blockIdx.x * blockDim.x + threadIdx.x;
    if (idx >= TK * FF) return;
    int p = idx >> 10, j = idx & (FF - 1);
    float gv = g_gu[(size_t)p * (2*FF) + j];
    float uv = g_gu[(size_t)p * (2*FF) + FF + j];
    g_act[idx] = gv / (1.f + expf(-gv)) * uv;
}

// ---------------- grouped MoE down GEMM, scaled scatter to slot buffers --
__global__ __launch_bounds__(256) void moe_down_kernel(const float* __restrict__ moe_down_w)
{
    int e = blockIdx.z;
    int cnt = g_cnt[e];
    int bm = blockIdx.y * BM;
    if (bm >= cnt) return;
    int off = g_off[e];
    const float* A = g_act + (size_t)off * FF;
    const float* B = moe_down_w + (size_t)e * FF * H_DIM;
    const int N = H_DIM, K = FF;
    int bn = blockIdx.x * BN;

    __shared__ float As[BKD][BM];
    __shared__ float Bs[BKD][BN];
    int tid = threadIdx.x;
    int aRow = tid >> 1, aCol = (tid & 1) << 2;
    int bRow = tid >> 5, bCol = (tid & 31) << 2;
    int tx = tid & 15, ty = tid >> 4;

    bool aValid = (bm + aRow) < cnt;
    const float* aPtr = A + (size_t)(bm + aRow) * K + aCol;
    const float* bPtr = B + (size_t)bRow * N + bn + bCol;

    float4 aReg = aValid ? *(const float4*)aPtr : make_float4(0,0,0,0);
    float4 bReg = *(const float4*)bPtr;
    float acc[8][8] = {};
    int nk = K / BKD;
    for (int kt = 0; kt < nk; ++kt) {
        As[aCol+0][aRow] = aReg.x; As[aCol+1][aRow] = aReg.y;
        As[aCol+2][aRow] = aReg.z; As[aCol+3][aRow] = aReg.w;
        *(float4*)&Bs[bRow][bCol] = bReg;
        __syncthreads();
        if (kt + 1 < nk) {
            aReg = aValid ? *(const float4*)(aPtr + (size_t)(kt+1)*BKD) : make_float4(0,0,0,0);
            bReg = *(const float4*)(bPtr + (size_t)(kt+1)*BKD*N);
        }
        #pragma unroll
        for (int kk = 0; kk < BKD; ++kk) {
            float a[8], b[8];
            *(float4*)(a)   = *(const float4*)&As[kk][ty*8];
            *(float4*)(a+4) = *(const float4*)&As[kk][ty*8+4];
            *(float4*)(b)   = *(const float4*)&Bs[kk][tx*8];
            *(float4*)(b+4) = *(const float4*)&Bs[kk][tx*8+4];
            #pragma unroll
            for (int i = 0; i < 8; i++)
                #pragma unroll
                for (int j = 0; j < 8; j++)
                    acc[i][j] += a[i] * b[j];
        }
        __syncthreads();
    }
    #pragma unroll
    for (int i = 0; i < 8; i++) {
        int lrow = bm + ty*8 + i;
        if (lrow >= cnt) continue;
        int code = g_perm[off + lrow];
        int t = code >> 1, k = code & 1;
        float w = g_topw[code];
        float* cp = g_slot + (size_t)k * T_DIM * H_DIM + (size_t)t * H_DIM + bn + tx*8;
        float4 v0, v1;
        v0.x = acc[i][0]*w; v0.y = acc[i][1]*w; v0.z = acc[i][2]*w; v0.w = acc[i][3]*w;
        v1.x = acc[i][4]*w; v1.y = acc[i][5]*w; v1.z = acc[i][6]*w; v1.w = acc[i][7]*w;
        *(float4*)(cp)   = v0;
        *(float4*)(cp+4) = v1;
    }
}

// ---------------- shared-FFN GLU ----------------
__global__ void glu_kernel()
{
    int idx = blockIdx.x * blockDim.x + threadIdx.x;
    if (idx >= T_DIM * SF) return;
    int t = idx >> 12, j = idx & (SF - 1);
    float gv = g_sg[(size_t)t * (2*SF) + j];
    float uv = g_sg[(size_t)t * (2*SF) + SF + j];
    g_mid[idx] = gv / (1.f + expf(-gv)) * uv;
}

// ---------------- final: out = x1 + slot0 + slot1 + shared_out -----------
__global__ void final_add_kernel(float* __restrict__ out)
{
    int i = blockIdx.x * blockDim.x + threadIdx.x;
    const float4* a = reinterpret_cast<const float4*>(g_x1);
    const float4* s0 = reinterpret_cast<const float4*>(g_slot);
    const float4* s1 = reinterpret_cast<const float4*>(g_slot + (size_t)T_DIM * H_DIM);
    const float4* sh = reinterpret_cast<const float4*>(g_sho);
    float4 va = a[i], v0 = s0[i], v1 = s1[i], vs = sh[i];
    float4 r;
    r.x = va.x + v0.x + v1.x + vs.x;
    r.y = va.y + v0.y + v1.y + vs.y;
    r.z = va.z + v0.z + v1.z + vs.z;
    r.w = va.w + v0.w + v1.w + vs.w;
    reinterpret_cast<float4*>(out)[i] = r;
}

// ---------------- host launcher ----------------
extern "C" void kernel_launch(void* const* d_in, const int* in_sizes, int n_in,
                              void* d_out, int out_size)
{
    (void)in_sizes; (void)n_in; (void)out_size;
    const float* x       = (const float*)d_in[0];
    const float* gamma1  = (const float*)d_in[1];
    const float* gamma2  = (const float*)d_in[2];
    const float* w_qkv   = (const float*)d_in[3];
    const float* w_o     = (const float*)d_in[4];
    const float* gate_w  = (const float*)d_in[5];
    const float* moe_upw = (const float*)d_in[6];
    const float* moe_dnw = (const float*)d_in[7];
    const float* w13     = (const float*)d_in[8];
    const float* wdown   = (const float*)d_in[9];
    float* out = (float*)d_out;

    float *ph, *pqkv, *pctx, *px1, *ph2, *psg, *pmid, *psho;
    cudaGetSymbolAddress((void**)&ph,   g_h);
    cudaGetSymbolAddress((void**)&pqkv, g_qkv);
    cudaGetSymbolAddress((void**)&pctx, g_ctx);
    cudaGetSymbolAddress((void**)&px1,  g_x1);
    cudaGetSymbolAddress((void**)&ph2,  g_h2);
    cudaGetSymbolAddress((void**)&psg,  g_sg);
    cudaGetSymbolAddress((void**)&pmid, g_mid);
    cudaGetSymbolAddress((void**)&psho, g_sho);

    const int flash_smem = FL_SMEM_FLOATS * 4;
    cudaFuncSetAttribute(flash_kernel, cudaFuncAttributeMaxDynamicSharedMemorySize, flash_smem);

    // 1. h = rmsnorm(x, gamma1)
    rmsnorm_kernel<<<T_DIM, 256>>>(x, gamma1, ph);
    // 2. qkv = h @ w_qkv
    sgemm_kernel<0><<<dim3(3*H_DIM/BN, T_DIM/BM), 256>>>(ph, w_qkv, pqkv, nullptr, T_DIM, 3*H_DIM, H_DIM);
    // 3. RoPE
    rope_kernel<<<(T_DIM*NHEAD*64 + 255)/256, 256>>>();
    // 4. flash attention -> ctx
    flash_kernel<<<dim3(T_DIM/64, NHEAD), 256, flash_smem>>>();
    // 5. x1 = x + ctx @ w_o
    sgemm_kernel<1><<<dim3(H_DIM/BN, T_DIM/BM), 256>>>(pctx, w_o, px1, x, T_DIM, H_DIM, H_DIM);
    // 6. h2 = rmsnorm(x1, gamma2)
    rmsnorm_kernel<<<T_DIM, 256>>>(px1, gamma2, ph2);
    // 7. router (top-2)
    router_kernel<<<T_DIM/8, 256>>>(gate_w);
    // 8-11. expert grouping
    zero_cnt_kernel<<<1, 32>>>();
    count_kernel<<<(TK + 255)/256, 256>>>();
    scan_kernel<<<1, 32>>>();
    scatter_kernel<<<(TK + 255)/256, 256>>>();
    // 12. moe up (grouped)
    moe_up_kernel<<<dim3(2*FF/BN, TK/BM, NE), 256>>>(moe_upw);
    // 13. moe activation
    moe_act_kernel<<<(TK*FF + 255)/256, 256>>>();
    // 14. moe down (grouped, scaled scatter)
    moe_down_kernel<<<dim3(H_DIM/BN, TK/BM, NE), 256>>>(moe_dnw);
    // 15. shared ffn up
    sgemm_kernel<0><<<dim3(2*SF/BN, T_DIM/BM), 256>>>(ph2, w13, psg, nullptr, T_DIM, 2*SF, H_DIM);
    // 16. shared glu
    glu_kernel<<<(T_DIM*SF + 255)/256, 256>>>();
    // 17. shared ffn down
    sgemm_kernel<0><<<dim3(H_DIM/BN, T_DIM/BM), 256>>>(pmid, wdown, psho, nullptr, T_DIM, H_DIM, SF);
    // 18. final sum
    final_add_kernel<<<(T_DIM*H_DIM/4 + 255)/256, 256>>>(out);
}

// round 2
// speedup vs baseline: 2.2268x; 2.2268x over previous
#include <cuda_runtime.h>
#include <cuda_bf16.h>
#include <math.h>
#include <stdint.h>

// ---------------- problem constants ----------------
#define T_DIM 2048
#define H_DIM 2048
#define NHEAD 16
#define HD    128
#define NE    16
#define FF    1024
#define SF    4096
#define TK    (T_DIM * 2)

typedef __nv_bfloat16 bf16;
typedef __nv_bfloat162 bf162;

// ---------------- fp32 scratch ----------------
__device__ float g_qkv [T_DIM * 3 * H_DIM];
__device__ float g_x1  [T_DIM * H_DIM];
__device__ float g_h2f [T_DIM * H_DIM];
__device__ float g_sg  [T_DIM * 2 * SF];
__device__ float g_sho [T_DIM * H_DIM];
__device__ float g_gu  [TK * 2 * FF];
__device__ float g_slot[2 * T_DIM * H_DIM];

// ---------------- bf16 hi/lo planes (activations) ----------------
__device__ bf16 g_h_hi  [T_DIM * H_DIM], g_h_lo  [T_DIM * H_DIM];
__device__ bf16 g_ctx_hi[T_DIM * H_DIM], g_ctx_lo[T_DIM * H_DIM];
__device__ bf16 g_h2_hi [T_DIM * H_DIM], g_h2_lo [T_DIM * H_DIM];
__device__ bf16 g_mid_hi[T_DIM * SF],    g_mid_lo[T_DIM * SF];
__device__ bf16 g_act_hi[TK * FF],       g_act_lo[TK * FF];

// ---------------- bf16 hi/lo planes (weights) ----------------
__device__ bf16 w_qkv_hi[H_DIM * 3 * H_DIM], w_qkv_lo[H_DIM * 3 * H_DIM];
__device__ bf16 w_o_hi  [H_DIM * H_DIM],     w_o_lo  [H_DIM * H_DIM];
__device__ bf16 w_up_hi [NE * H_DIM * 2 * FF], w_up_lo [NE * H_DIM * 2 * FF];
__device__ bf16 w_dn_hi [NE * FF * H_DIM],     w_dn_lo [NE * FF * H_DIM];
__device__ bf16 w_13_hi [H_DIM * 2 * SF],      w_13_lo [H_DIM * 2 * SF];
__device__ bf16 w_d2_hi [SF * H_DIM],          w_d2_lo [SF * H_DIM];

// ---------------- routing scratch ----------------
__device__ int   g_topi[TK];
__device__ float g_topw[TK];
__device__ int   g_cnt[NE], g_off[NE], g_cur[NE], g_perm[TK];

// ---------------- split helpers ----------------
__device__ __forceinline__ void wr2(bf16* __restrict__ hi, bf16* __restrict__ lo,
                                    size_t idx, float u, float v)
{
    bf16 uh = __float2bfloat16_rn(u);
    bf16 vh = __float2bfloat16_rn(v);
    float ur = u - __bfloat162float(uh);
    float vr = v - __bfloat162float(vh);
    *(bf162*)(hi + idx) = __halves2bfloat162(uh, vh);
    *(bf162*)(lo + idx) = __halves2bfloat162(__float2bfloat16_rn(ur), __float2bfloat16_rn(vr));
}

__global__ __launch_bounds__(256) void cvt_kernel(
    const float* __restrict__ x, bf16* __restrict__ hi, bf16* __restrict__ lo, long n4)
{
    long i = (long)blockIdx.x * blockDim.x + threadIdx.x;
    if (i >= n4) return;
    float4 v = reinterpret_cast<const float4*>(x)[i];
    wr2(hi, lo, i * 4,     v.x, v.y);
    wr2(hi, lo, i * 4 + 2, v.z, v.w);
}

// ---------------- rmsnorm + split ----------------
template<bool F32>
__global__ __launch_bounds__(256) void rmsnorm_cvt_kernel(
    const float* __restrict__ x, const float* __restrict__ g,
    float* __restrict__ of, bf16* __restrict__ ohi, bf16* __restrict__ olo)
{
    int row = blockIdx.x;
    int tid = threadIdx.x;
    const float4* xr = reinterpret_cast<const float4*>(x + (size_t)row * H_DIM);
    const float4* gr = reinterpret_cast<const float4*>(g);

    float4 a = xr[tid];
    float4 b = xr[tid + 256];
    float ss = a.x*a.x + a.y*a.y + a.z*a.z + a.w*a.w
             + b.x*b.x + b.y*b.y + b.z*b.z + b.w*b.w;
    #pragma unroll
    for (int off = 16; off; off >>= 1) ss += __shfl_xor_sync(0xffffffffu, ss, off);
    __shared__ float red[8];
    if ((tid & 31) == 0) red[tid >> 5] = ss;
    __syncthreads();
    float tot = 0.f;
    #pragma unroll
    for (int i = 0; i < 8; i++) tot += red[i];
    float inv = rsqrtf(tot * (1.0f / H_DIM) + 1e-6f);
    float4 ga = gr[tid], gb = gr[tid + 256];
    float4 oa, ob;
    oa.x = a.x*inv*ga.x; oa.y = a.y*inv*ga.y; oa.z = a.z*inv*ga.z; oa.w = a.w*inv*ga.w;
    ob.x = b.x*inv*gb.x; ob.y = b.y*inv*gb.y; ob.z = b.z*inv*gb.z; ob.w = b.w*inv*gb.w;
    size_t base = (size_t)row * H_DIM;
    if (F32) {
        reinterpret_cast<float4*>(of + base)[tid] = oa;
        reinterpret_cast<float4*>(of + base)[tid + 256] = ob;
    }
    size_t c0 = base + (size_t)tid * 4, c1 = base + (size_t)(tid + 256) * 4;
    wr2(ohi, olo, c0,     oa.x, oa.y);
    wr2(ohi, olo, c0 + 2, oa.z, oa.w);
    wr2(ohi, olo, c1,     ob.x, ob.y);
    wr2(ohi, olo, c1 + 2, ob.z, ob.w);
}

// ================= tensor-core GEMM (bf16 split, mma.sync m16n8k16) =======
// BM=128 BN=128 BK=32, 8 warps (2x4), warp tile 64x32.
// smem per stage (bf16 elems): A_hi[128][40]=5120, A_lo=5120, B_hi[32][136]=4352, B_lo=4352
// byte offsets: A_hi 0, A_lo 10240, B_hi 20480, B_lo 29184, stage stride 37888.

__device__ __forceinline__ void cp16(uint32_t dst, const void* src, bool v)
{
    if (v) asm volatile("cp.async.cg.shared.global [%0], [%1], 16;\n" :: "r"(dst), "l"(src));
    else   asm volatile("st.shared.v4.b32 [%0], {%1,%1,%1,%1};\n" :: "r"(dst), "r"(0u));
}

#define MMA_BF16(d, a, b0_, b1_) \
    asm volatile("mma.sync.aligned.m16n8k16.row.col.f32.bf16.bf16.f32 " \
        "{%0,%1,%2,%3},{%4,%5,%6,%7},{%8,%9},{%0,%1,%2,%3};" \
        : "+f"(d[0]), "+f"(d[1]), "+f"(d[2]), "+f"(d[3]) \
        : "r"(a[0]), "r"(a[1]), "r"(a[2]), "r"(a[3]), "r"(b0_), "r"(b1_))

// MODE: 0 plain store, 1 +residual, 2 MoE-up (gather A rows via perm), 3 MoE-down (scaled scatter)
template<int MODE>
__global__ __launch_bounds__(256) void mma_gemm(
    const bf16* __restrict__ Ahi, const bf16* __restrict__ Alo,
    const bf16* __restrict__ Bhi, const bf16* __restrict__ Blo,
    float* __restrict__ C, const float* __restrict__ R,
    int M, int N, int K)
{
    int off = 0;
    if (MODE >= 2) {
        int e = blockIdx.z;
        M = g_cnt[e]; off = g_off[e];
        size_t w = (size_t)K * N;
        Bhi += (size_t)e * w; Blo += (size_t)e * w;
        if (MODE == 3) { Ahi += (size_t)off * K; Alo += (size_t)off * K; }
    }
    int bm = blockIdx.y * 128;
    if (bm >= M) return;
    int bn = blockIdx.x * 128;

    extern __shared__ char smch[];
    uint32_t smem = (uint32_t)__cvta_generic_to_shared(smch);

    int tid = threadIdx.x, lane = tid & 31, warp = tid >> 5;

    // global->smem mapping (2 chunks/thread/plane)
    int ar0 = tid >> 2, ac = (tid & 3) << 3;
    int ar1 = ar0 + 64;
    int br0 = tid >> 4, bc = (tid & 15) << 3;
    int br1 = br0 + 16;
    bool av0 = (bm + ar0) < M, av1 = (bm + ar1) < M;
    long ra0, ra1;
    if (MODE == 2) {
        ra0 = av0 ? (long)(g_perm[off + bm + ar0] >> 1) * K : 0;
        ra1 = av1 ? (long)(g_perm[off + bm + ar1] >> 1) * K : 0;
    } else {
        ra0 = (long)(av0 ? bm + ar0 : 0) * K;
        ra1 = (long)(av1 ? bm + ar1 : 0) * K;
    }
    const bf16 *pa0h = Ahi + ra0 + ac, *pa1h = Ahi + ra1 + ac;
    const bf16 *pa0l = Alo + ra0 + ac, *pa1l = Alo + ra1 + ac;
    const bf16 *pb0h = Bhi + (size_t)br0 * N + bn + bc, *pb1h = Bhi + (size_t)br1 * N + bn + bc;
    const bf16 *pb0l = Blo + (size_t)br0 * N + bn + bc, *pb1l = Blo + (size_t)br1 * N + bn + bc;
    uint32_t sa0 = (uint32_t)(ar0 * 40 + ac) * 2, sa1 = (uint32_t)(ar1 * 40 + ac) * 2;
    uint32_t sb0 = (uint32_t)(br0 * 136 + bc) * 2, sb1 = (uint32_t)(br1 * 136 + bc) * 2;

    auto load_tile = [&](int stage, int kt) {
        uint32_t b = smem + stage * 37888;
        long ko = (long)kt * 32;
        long kb = ko * N;
        cp16(b + sa0,          pa0h + ko, av0);
        cp16(b + sa1,          pa1h + ko, av1);
        cp16(b + 10240 + sa0,  pa0l + ko, av0);
        cp16(b + 10240 + sa1,  pa1l + ko, av1);
        cp16(b + 20480 + sb0,  pb0h + kb, true);
        cp16(b + 20480 + sb1,  pb1h + kb, true);
        cp16(b + 29184 + sb0,  pb0l + kb, true);
        cp16(b + 29184 + sb1,  pb1l + kb, true);
        asm volatile("cp.async.commit_group;\n" ::);
    };

    int m0 = (warp >> 2) * 64, n0 = (warp & 3) * 32;
    float acc[4][4][4] = {};

    uint32_t a_off = (uint32_t)((m0 + (lane & 15)) * 40 + ((lane >> 4) << 3)) * 2;
    uint32_t b_off = (uint32_t)((lane & 15) * 136 + n0) * 2;

    int nk = K >> 5;
    load_tile(0, 0);
    for (int kt = 0; kt < nk; ++kt) {
        int buf = kt & 1;
        if (kt + 1 < nk) {
            load_tile(buf ^ 1, kt + 1);
            asm volatile("cp.async.wait_group 1;\n" ::);
        } else {
            asm volatile("cp.async.wait_group 0;\n" ::);
        }
        __syncthreads();
        uint32_t sbase = smem + buf * 37888;
        #pragma unroll
        for (int kk = 0; kk < 2; ++kk) {
            uint32_t ah[4][4], al[4][4];
            #pragma unroll
            for (int i = 0; i < 4; ++i) {
                uint32_t addr = sbase + a_off + (uint32_t)(i * 640 + kk * 16) * 2;
                asm volatile("ldmatrix.sync.aligned.m8n8.x4.shared.b16 {%0,%1,%2,%3}, [%4];"
                    : "=r"(ah[i][0]), "=r"(ah[i][1]), "=r"(ah[i][2]), "=r"(ah[i][3]) : "r"(addr));
                asm volatile("ldmatrix.sync.aligned.m8n8.x4.shared.b16 {%0,%1,%2,%3}, [%4];"
                    : "=r"(al[i][0]), "=r"(al[i][1]), "=r"(al[i][2]), "=r"(al[i][3]) : "r"(addr + 10240));
            }
            #pragma unroll
            for (int j = 0; j < 4; ++j) {
                uint32_t baddr = sbase + 20480 + b_off + (uint32_t)(kk * 2176 + j * 8) * 2;
                uint32_t bh0, bh1, bl0, bl1;
                asm volatile("ldmatrix.sync.aligned.m8n8.x2.trans.shared.b16 {%0,%1}, [%2];"
                    : "=r"(bh0), "=r"(bh1) : "r"(baddr));
                asm volatile("ldmatrix.sync.aligned.m8n8.x2.trans.shared.b16 {%0,%1}, [%2];"
                    : "=r"(bl0), "=r"(bl1) : "r"(baddr + 8704));
                #pragma unroll
                for (int i = 0; i < 4; ++i) {
                    MMA_BF16(acc[i][j], ah[i], bh0, bh1);
                    MMA_BF16(acc[i][j], ah[i], bl0, bl1);
                    MMA_BF16(acc[i][j], al[i], bh0, bh1);
                }
            }
        }
        __syncthreads();
    }

    // epilogue
    int tq = lane >> 2, tr = lane & 3;
    #pragma unroll
    for (int i = 0; i < 4; ++i) {
        #pragma unroll
        for (int h = 0; h < 2; ++h) {
            int row = bm + m0 + i * 16 + tq + h * 8;
            if (MODE >= 2 && row >= M) continue;
            size_t drow; float w = 1.f;
            if (MODE == 2)      drow = (size_t)(off + row);
            else if (MODE == 3) {
                int code = g_perm[off + row];
                w = g_topw[code];
                drow = (size_t)((code & 1) * T_DIM + (code >> 1));
            }
            else                drow = (size_t)row;
            float* cp = C + drow * N + bn + n0 + tr * 2;
            #pragma unroll
            for (int j = 0; j < 4; ++j) {
                float v0 = acc[i][j][h * 2], v1 = acc[i][j][h * 2 + 1];
                if (MODE == 1) {
                    const float* rp = R + (size_t)row * N + bn + n0 + tr * 2 + j * 8;
                    v0 += rp[0]; v1 += rp[1];
                }
                if (MODE == 3) { v0 *= w; v1 *= w; }
                *(float2*)(cp + j * 8) = make_float2(v0, v1);
            }
        }
    }
}

// ---------------- RoPE (in-place on q,k inside g_qkv) ----------------
__global__ void rope_kernel()
{
    int idx = blockIdx.x * blockDim.x + threadIdx.x;
    if (idx >= T_DIM * NHEAD * (HD/2)) return;
    int d = idx & 63;
    int h = (idx >> 6) & 15;
    int t = idx >> 10;
    float freq = powf(10000.0f, -(float)d * (1.0f/64.0f));
    float ang = (float)t * freq;
    float s, c;
    sincosf(ang, &s, &c);
    float* q = g_qkv + (size_t)t * (3*H_DIM) + h * HD + d;
    float q1 = q[0], q2 = q[64];
    q[0]  = q1*c - q2*s;
    q[64] = q1*s + q2*c;
    float* k = q + H_DIM;
    float k1 = k[0], k2 = k[64];
    k[0]  = k1*c - k2*s;
    k[64] = k1*s + k2*c;
}

// ---------------- causal flash attention (fp32) ----------------
#define FL_SMEM_FLOATS (64*128 + 64*129 + 64*128 + 64*65 + 64 + 64)
__global__ __launch_bounds__(256) void flash_kernel()
{
    extern __shared__ float sm[];
    float* Qs = sm;
    float* Ks = Qs + 64*128;
    float* Vs = Ks + 64*129;
    float* Ss = Vs + 64*128;
    float* Al = Ss + 64*65;
    float* Lf = Al + 64;

    int qt = blockIdx.x, head = blockIdx.y;
    int tid = threadIdx.x, lane = tid & 31, warp = tid >> 5;
    const float scale = 0.08838834764831845f;

    for (int it = tid; it < 64*32; it += 256) {
        int r = it >> 5, cs = (it & 31) << 2;
        float4 v = *(const float4*)(g_qkv + (size_t)(qt*64 + r)*(3*H_DIM) + head*HD + cs);
        float* qp = Qs + r*128 + cs;
        qp[0]=v.x*scale; qp[1]=v.y*scale; qp[2]=v.z*scale; qp[3]=v.w*scale;
    }

    float m_r = -1e30f, l_r = 0.f;
    float o0[16], o1[16];
    #pragma unroll
    for (int j = 0; j < 16; j++) { o0[j] = 0.f; o1[j] = 0.f; }
    int rr0 = lane, rr1 = lane + 32, db = warp * 16;

    for (int kt = 0; kt <= qt; ++kt) {
        for (int it = tid; it < 64*32; it += 256) {
            int r = it >> 5, cs = (it & 31) << 2;
            const float* kp = g_qkv + (size_t)(kt*64 + r)*(3*H_DIM) + H_DIM + head*HD + cs;
            float4 kv = *(const float4*)kp;
            float* kd = Ks + r*129 + cs;
            kd[0]=kv.x; kd[1]=kv.y; kd[2]=kv.z; kd[3]=kv.w;
            *(float4*)(Vs + r*128 + cs) = *(const float4*)(kp + H_DIM);
        }
        __syncthreads();

        float acc[8][2];
        #pragma unroll
        for (int i = 0; i < 8; i++) { acc[i][0] = 0.f; acc[i][1] = 0.f; }
        const float* k0p = Ks + lane*129;
        const float* k1p = Ks + (lane+32)*129;
        const float* q0p = Qs + (warp*8)*128;
        #pragma unroll 4
        for (int d = 0; d < 128; ++d) {
            float k0 = k0p[d], k1 = k1p[d];
            #pragma unroll
            for (int i = 0; i < 8; i++) {
                float q = q0p[i*128 + d];
                acc[i][0] += q * k0;
                acc[i][1] += q * k1;
            }
        }
        bool diag = (kt == qt);
        #pragma unroll
        for (int i = 0; i < 8; i++) {
            int r = warp*8 + i;
            float s0 = acc[i][0], s1 = acc[i][1];
            if (diag) {
                if (lane > r)      s0 = -1e30f;
                if (lane + 32 > r) s1 = -1e30f;
            }
            Ss[r*65 + lane]      = s0;
            Ss[r*65 + lane + 32] = s1;
        }
        __syncthreads();

        if (tid < 64) {
            float* srow = Ss + tid*65;
            float mx = m_r;
            #pragma unroll 8
            for (int c = 0; c < 64; c++) mx = fmaxf(mx, srow[c]);
            float al = __expf(m_r - mx);
            float sum = 0.f;
            #pragma unroll 4
            for (int c = 0; c < 64; c++) {
                float p = __expf(srow[c] - mx);
                srow[c] = p;
                sum += p;
            }
            l_r = l_r * al + sum;
            m_r = mx;
            Al[tid] = al;
        }
        __syncthreads();

        float a0 = Al[rr0], a1 = Al[rr1];
        #pragma unroll
        for (int j = 0; j < 16; j++) { o0[j] *= a0; o1[j] *= a1; }
        #pragma unroll 2
        for (int c = 0; c < 64; c++) {
            float p0 = Ss[rr0*65 + c], p1 = Ss[rr1*65 + c];
            const float* vp = Vs + c*128 + db;
            #pragma unroll
            for (int j = 0; j < 16; j++) {
                float v = vp[j];
                o0[j] += p0 * v;
                o1[j] += p1 * v;
            }
        }
        __syncthreads();
    }

    if (tid < 64) Lf[tid] = l_r;
    __syncthreads();
    float inv0 = 1.f / Lf[rr0], inv1 = 1.f / Lf[rr1];
    size_t b0 = (size_t)(qt*64 + rr0) * H_DIM + head*HD + db;
    size_t b1 = (size_t)(qt*64 + rr1) * H_DIM + head*HD + db;
    #pragma unroll
    for (int j = 0; j < 16; j += 2) {
        wr2(g_ctx_hi, g_ctx_lo, b0 + j, o0[j]*inv0, o0[j+1]*inv0);
        wr2(g_ctx_hi, g_ctx_lo, b1 + j, o1[j]*inv1, o1[j+1]*inv1);
    }
}

// ---------------- router: logits + softmax-top2 (1 warp / token) --------
__global__ __launch_bounds__(256) void router_kernel(const float* __restrict__ gate_w)
{
    int gwarp = (blockIdx.x * blockDim.x + threadIdx.x) >> 5;
    int lane = threadIdx.x & 31;
    if (gwarp >= T_DIM) return;
    const float* hrow = g_h2f + (size_t)gwarp * H_DIM;
    float acc[NE];
    #pragma unroll
    for (int e = 0; e < NE; e++) acc[e] = 0.f;
    for (int i = lane; i < H_DIM; i += 32) {
        float hv = hrow[i];
        const float4* gw = reinterpret_cast<const float4*>(gate_w + (size_t)i * NE);
        #pragma unroll
        for (int q = 0; q < 4; q++) {
            float4 g4 = gw[q];
            acc[q*4+0] += hv * g4.x;
            acc[q*4+1] += hv * g4.y;
            acc[q*4+2] += hv * g4.z;
            acc[q*4+3] += hv * g4.w;
        }
    }
    #pragma unroll
    for (int e = 0; e < NE; e++)
        #pragma unroll
        for (int off = 16; off; off >>= 1)
            acc[e] += __shfl_xor_sync(0xffffffffu, acc[e], off);
    if (lane == 0) {
        float best = -1e30f; int bi = 0;
        #pragma unroll
        for (int e = 0; e < NE; e++) if (acc[e] > best) { best = acc[e]; bi = e; }
        float best2 = -1e30f; int bi2 = 0;
        #pragma unroll
        for (int e = 0; e < NE; e++) if (e != bi && acc[e] > best2) { best2 = acc[e]; bi2 = e; }
        float e1 = expf(best2 - best);
        float w0 = 1.f / (1.f + e1);
        float w1 = e1 / (1.f + e1);
        g_topi[2*gwarp]   = bi;  g_topw[2*gwarp]   = w0;
        g_topi[2*gwarp+1] = bi2; g_topw[2*gwarp+1] = w1;
    }
}

// ---------------- expert grouping ----------------
__global__ void zero_cnt_kernel() {
    int i = threadIdx.x;
    if (i < NE) { g_cnt[i] = 0; g_cur[i] = 0; }
}
__global__ void count_kernel() {
    int i = blockIdx.x * blockDim.x + threadIdx.x;
    if (i < TK) atomicAdd(&g_cnt[g_topi[i]], 1);
}
__global__ void scan_kernel() {
    if (threadIdx.x == 0) {
        int o = 0;
        for (int e = 0; e < NE; e++) { g_off[e] = o; g_cur[e] = o; o += g_cnt[e]; }
    }
}
__global__ void scatter_kernel() {
    int i = blockIdx.x * blockDim.x + threadIdx.x;
    if (i < TK) {
        int e = g_topi[i];
        int p = atomicAdd(&g_cur[e], 1);
        g_perm[p] = i;
    }
}

// ---------------- moe activation: act = silu(g)*u (bf16 split out) -------
__global__ void moe_act_kernel()
{
    long i = ((long)blockIdx.x * blockDim.x + threadIdx.x) * 2;
    if (i >= (long)TK * FF) return;
    long p = i >> 10;
    int  j = (int)(i & 1023);
    const float* gp = g_gu + p * (2*FF);
    float g0 = gp[j],        g1 = gp[j+1];
    float u0 = gp[FF + j],   u1 = gp[FF + j + 1];
    float a0 = g0 / (1.f + expf(-g0)) * u0;
    float a1 = g1 / (1.f + expf(-g1)) * u1;
    wr2(g_act_hi, g_act_lo, (size_t)i, a0, a1);
}

// ---------------- shared-FFN GLU (bf16 split out) ----------------
__global__ void glu_kernel()
{
    long i = ((long)blockIdx.x * blockDim.x + threadIdx.x) * 2;
    if (i >= (long)T_DIM * SF) return;
    long t = i >> 12;
    int  j = (int)(i & (SF - 1));
    const float* gp = g_sg + t * (2*SF);
    float g0 = gp[j],       g1 = gp[j+1];
    float u0 = gp[SF + j],  u1 = gp[SF + j + 1];
    float a0 = g0 / (1.f + expf(-g0)) * u0;
    float a1 = g1 / (1.f + expf(-g1)) * u1;
    wr2(g_mid_hi, g_mid_lo, (size_t)i, a0, a1);
}

// ---------------- final: out = x1 + slot0 + slot1 + shared_out -----------
__global__ void final_add_kernel(float* __restrict__ out)
{
    int i = blockIdx.x * blockDim.x + threadIdx.x;
    const float4* a  = reinterpret_cast<const float4*>(g_x1);
    const float4* s0 = reinterpret_cast<const float4*>(g_slot);
    const float4* s1 = reinterpret_cast<const float4*>(g_slot + (size_t)T_DIM * H_DIM);
    const float4* sh = reinterpret_cast<const float4*>(g_sho);
    float4 va = a[i], v0 = s0[i], v1 = s1[i], vs = sh[i];
    float4 r;
    r.x = va.x + v0.x + v1.x + vs.x;
    r.y = va.y + v0.y + v1.y + vs.y;
    r.z = va.z + v0.z + v1.z + vs.z;
    r.w = va.w + v0.w + v1.w + vs.w;
    reinterpret_cast<float4*>(out)[i] = r;
}

// ---------------- host launcher ----------------
#define GETSYM(p, s) cudaGetSymbolAddress((void**)&p, s)

extern "C" void kernel_launch(void* const* d_in, const int* in_sizes, int n_in,
                              void* d_out, int out_size)
{
    (void)in_sizes; (void)n_in; (void)out_size;
    const float* x       = (const float*)d_in[0];
    const float* gamma1  = (const float*)d_in[1];
    const float* gamma2  = (const float*)d_in[2];
    const float* w_qkv   = (const float*)d_in[3];
    const float* w_o     = (const float*)d_in[4];
    const float* gate_w  = (const float*)d_in[5];
    const float* moe_upw = (const float*)d_in[6];
    const float* moe_dnw = (const float*)d_in[7];
    const float* w13     = (const float*)d_in[8];
    const float* wdown   = (const float*)d_in[9];
    float* out = (float*)d_out;

    float *pqkv, *px1, *ph2f, *psg, *psho, *pgu, *pslot;
    GETSYM(pqkv, g_qkv); GETSYM(px1, g_x1); GETSYM(ph2f, g_h2f);
    GETSYM(psg, g_sg);   GETSYM(psho, g_sho); GETSYM(pgu, g_gu); GETSYM(pslot, g_slot);

    bf16 *h_hi,*h_lo,*ctx_hi,*ctx_lo,*h2_hi,*h2_lo,*mid_hi,*mid_lo,*act_hi,*act_lo;
    GETSYM(h_hi, g_h_hi);   GETSYM(h_lo, g_h_lo);
    GETSYM(ctx_hi, g_ctx_hi); GETSYM(ctx_lo, g_ctx_lo);
    GETSYM(h2_hi, g_h2_hi); GETSYM(h2_lo, g_h2_lo);
    GETSYM(mid_hi, g_mid_hi); GETSYM(mid_lo, g_mid_lo);
    GETSYM(act_hi, g_act_hi); GETSYM(act_lo, g_act_lo);

    bf16 *wq_hi,*wq_lo,*wo_hi,*wo_lo,*wu_hi,*wu_lo,*wd_hi,*wd_lo,*w13_hi,*w13_lo,*wd2_hi,*wd2_lo;
    GETSYM(wq_hi, w_qkv_hi); GETSYM(wq_lo, w_qkv_lo);
    GETSYM(wo_hi, w_o_hi);   GETSYM(wo_lo, w_o_lo);
    GETSYM(wu_hi, w_up_hi);  GETSYM(wu_lo, w_up_lo);
    GETSYM(wd_hi, w_dn_hi);  GETSYM(wd_lo, w_dn_lo);
    GETSYM(w13_hi, w_13_hi); GETSYM(w13_lo, w_13_lo);
    GETSYM(wd2_hi, w_d2_hi); GETSYM(wd2_lo, w_d2_lo);

    const int gemm_smem = 75776;
    cudaFuncSetAttribute(mma_gemm<0>, cudaFuncAttributeMaxDynamicSharedMemorySize, gemm_smem);
    cudaFuncSetAttribute(mma_gemm<1>, cudaFuncAttributeMaxDynamicSharedMemorySize, gemm_smem);
    cudaFuncSetAttribute(mma_gemm<2>, cudaFuncAttributeMaxDynamicSharedMemorySize, gemm_smem);
    cudaFuncSetAttribute(mma_gemm<3>, cudaFuncAttributeMaxDynamicSharedMemorySize, gemm_smem);
    const int flash_smem = FL_SMEM_FLOATS * 4;
    cudaFuncSetAttribute(flash_kernel, cudaFuncAttributeMaxDynamicSharedMemorySize, flash_smem);

    // weight splits (hi/lo bf16 planes)
    auto cvt = [&](const float* src, bf16* hi, bf16* lo, long n) {
        long n4 = n / 4;
        cvt_kernel<<<(unsigned)((n4 + 255) / 256), 256>>>(src, hi, lo, n4);
    };
    cvt(w_qkv,   wq_hi,  wq_lo,  (long)H_DIM * 3 * H_DIM);
    cvt(w_o,     wo_hi,  wo_lo,  (long)H_DIM * H_DIM);
    cvt(moe_upw, wu_hi,  wu_lo,  (long)NE * H_DIM * 2 * FF);
    cvt(moe_dnw, wd_hi,  wd_lo,  (long)NE * FF * H_DIM);
    cvt(w13,     w13_hi, w13_lo, (long)H_DIM * 2 * SF);
    cvt(wdown,   wd2_hi, wd2_lo, (long)SF * H_DIM);

    // 1. h = rmsnorm(x, gamma1) -> bf16 planes
    rmsnorm_cvt_kernel<false><<<T_DIM, 256>>>(x, gamma1, nullptr, h_hi, h_lo);
    // 2. qkv = h @ w_qkv (tensor cores)
    mma_gemm<0><<<dim3(3*H_DIM/128, T_DIM/128, 1), 256, gemm_smem>>>(
        h_hi, h_lo, wq_hi, wq_lo, pqkv, nullptr, T_DIM, 3*H_DIM, H_DIM);
    // 3. RoPE
    rope_kernel<<<(T_DIM*NHEAD*64 + 255)/256, 256>>>();
    // 4. flash attention -> ctx planes
    flash_kernel<<<dim3(T_DIM/64, NHEAD), 256, flash_smem>>>();
    // 5. x1 = x + ctx @ w_o
    mma_gemm<1><<<dim3(H_DIM/128, T_DIM/128, 1), 256, gemm_smem>>>(
        ctx_hi, ctx_lo, wo_hi, wo_lo, px1, x, T_DIM, H_DIM, H_DIM);
    // 6. h2 = rmsnorm(x1, gamma2) -> fp32 + planes
    rmsnorm_cvt_kernel<true><<<T_DIM, 256>>>(px1, gamma2, ph2f, h2_hi, h2_lo);
    // 7. router (top-2)
    router_kernel<<<T_DIM/8, 256>>>(gate_w);
    // 8-11. expert grouping
    zero_cnt_kernel<<<1, 32>>>();
    count_kernel<<<(TK + 255)/256, 256>>>();
    scan_kernel<<<1, 32>>>();
    scatter_kernel<<<(TK + 255)/256, 256>>>();
    // 12. moe up (grouped, gathered)
    mma_gemm<2><<<dim3(2*FF/128, TK/128, NE), 256, gemm_smem>>>(
        h2_hi, h2_lo, wu_hi, wu_lo, pgu, nullptr, TK, 2*FF, H_DIM);
    // 13. moe activation -> act planes
    moe_act_kernel<<<(unsigned)(((long)TK*FF/2 + 255)/256), 256>>>();
    // 14. moe down (grouped, scaled scatter)
    mma_gemm<3><<<dim3(H_DIM/128, TK/128, NE), 256, gemm_smem>>>(
        act_hi, act_lo, wd_hi, wd_lo, pslot, nullptr, TK, H_DIM, FF);
    // 15. shared ffn up
    mma_gemm<0><<<dim3(2*SF/128, T_DIM/128, 1), 256, gemm_smem>>>(
        h2_hi, h2_lo, w13_hi, w13_lo, psg, nullptr, T_DIM, 2*SF, H_DIM);
    // 16. shared glu -> mid planes
    glu_kernel<<<(unsigned)(((long)T_DIM*SF/2 + 255)/256), 256>>>();
    // 17. shared ffn down
    mma_gemm<0><<<dim3(H_DIM/128, T_DIM/128, 1), 256, gemm_smem>>>(
        mid_hi, mid_lo, wd2_hi, wd2_lo, psho, nullptr, T_DIM, H_DIM, SF);
    // 18. final sum
    final_add_kernel<<<(T_DIM*H_DIM/4 + 255)/256, 256>>>(out);
}

// round 4
// speedup vs baseline: 2.7157x; 1.2195x over previous
#include <cuda_runtime.h>
#include <cuda_bf16.h>
#include <math.h>
#include <stdint.h>

// ---------------- problem constants ----------------
#define T_DIM 2048
#define H_DIM 2048
#define NHEAD 16
#define HD    128
#define NE    16
#define FF    1024
#define SF    4096
#define TK    (T_DIM * 2)

typedef __nv_bfloat16 bf16;
typedef __nv_bfloat162 bf162;

// ---------------- fp32 scratch ----------------
__device__ float g_qkv [T_DIM * 3 * H_DIM];
__device__ float g_x1  [T_DIM * H_DIM];
__device__ float g_h2f [T_DIM * H_DIM];
__device__ float g_sg  [T_DIM * 2 * SF];
__device__ float g_sho [T_DIM * H_DIM];
__device__ float g_gu  [TK * 2 * FF];
__device__ float g_slot[2 * T_DIM * H_DIM];

// ---------------- bf16 hi/lo planes (activations) ----------------
__device__ bf16 g_h_hi  [T_DIM * H_DIM], g_h_lo  [T_DIM * H_DIM];
__device__ bf16 g_ctx_hi[T_DIM * H_DIM], g_ctx_lo[T_DIM * H_DIM];
__device__ bf16 g_h2_hi [T_DIM * H_DIM], g_h2_lo [T_DIM * H_DIM];
__device__ bf16 g_mid_hi[T_DIM * SF],    g_mid_lo[T_DIM * SF];
__device__ bf16 g_act_hi[TK * FF],       g_act_lo[TK * FF];

// q/k/v planes, head-major [head][t][dim]
__device__ bf16 g_q_hi[NHEAD * T_DIM * HD], g_q_lo[NHEAD * T_DIM * HD];
__device__ bf16 g_k_hi[NHEAD * T_DIM * HD], g_k_lo[NHEAD * T_DIM * HD];
__device__ bf16 g_v_hi[NHEAD * T_DIM * HD], g_v_lo[NHEAD * T_DIM * HD];

// ---------------- bf16 hi/lo planes (weights, [K][N] layout) -------------
__device__ bf16 w_qkv_hi[H_DIM * 3 * H_DIM], w_qkv_lo[H_DIM * 3 * H_DIM];
__device__ bf16 w_o_hi  [H_DIM * H_DIM],     w_o_lo  [H_DIM * H_DIM];
__device__ bf16 w_up_hi [NE * H_DIM * 2 * FF], w_up_lo [NE * H_DIM * 2 * FF];
__device__ bf16 w_dn_hi [NE * FF * H_DIM],     w_dn_lo [NE * FF * H_DIM];
__device__ bf16 w_13_hi [H_DIM * 2 * SF],      w_13_lo [H_DIM * 2 * SF];
__device__ bf16 w_d2_hi [SF * H_DIM],          w_d2_lo [SF * H_DIM];

// ---------------- routing scratch ----------------
__device__ int   g_topi[TK];
__device__ float g_topw[TK];
__device__ int   g_cnt[NE], g_off[NE], g_cur[NE], g_perm[TK];

// ---------------- helpers ----------------
__device__ __forceinline__ void wr2(bf16* __restrict__ hi, bf16* __restrict__ lo,
                                    size_t idx, float u, float v)
{
    bf16 uh = __float2bfloat16_rn(u);
    bf16 vh = __float2bfloat16_rn(v);
    float ur = u - __bfloat162float(uh);
    float vr = v - __bfloat162float(vh);
    *(bf162*)(hi + idx) = __halves2bfloat162(uh, vh);
    *(bf162*)(lo + idx) = __halves2bfloat162(__float2bfloat16_rn(ur), __float2bfloat16_rn(vr));
}

__device__ __forceinline__ void split_pair(float f0, float f1, uint32_t& hi, uint32_t& lo)
{
    bf16 h0 = __float2bfloat16_rn(f0), h1 = __float2bfloat16_rn(f1);
    bf162 hv = __halves2bfloat162(h0, h1);
    float r0 = f0 - __bfloat162float(h0), r1 = f1 - __bfloat162float(h1);
    bf162 lv = __halves2bfloat162(__float2bfloat16_rn(r0), __float2bfloat16_rn(r1));
    hi = *(uint32_t*)&hv; lo = *(uint32_t*)&lv;
}

__global__ __launch_bounds__(256) void cvt_kernel(
    const float* __restrict__ x, bf16* __restrict__ hi, bf16* __restrict__ lo, long n4)
{
    long i = (long)blockIdx.x * blockDim.x + threadIdx.x;
    if (i >= n4) return;
    float4 v = reinterpret_cast<const float4*>(x)[i];
    wr2(hi, lo, i * 4,     v.x, v.y);
    wr2(hi, lo, i * 4 + 2, v.z, v.w);
}

// ---------------- rmsnorm + split ----------------
template<bool F32>
__global__ __launch_bounds__(256) void rmsnorm_cvt_kernel(
    const float* __restrict__ x, const float* __restrict__ g,
    float* __restrict__ of, bf16* __restrict__ ohi, bf16* __restrict__ olo)
{
    int row = blockIdx.x;
    int tid = threadIdx.x;
    const float4* xr = reinterpret_cast<const float4*>(x + (size_t)row * H_DIM);
    const float4* gr = reinterpret_cast<const float4*>(g);

    float4 a = xr[tid];
    float4 b = xr[tid + 256];
    float ss = a.x*a.x + a.y*a.y + a.z*a.z + a.w*a.w
             + b.x*b.x + b.y*b.y + b.z*b.z + b.w*b.w;
    #pragma unroll
    for (int off = 16; off; off >>= 1) ss += __shfl_xor_sync(0xffffffffu, ss, off);
    __shared__ float red[8];
    if ((tid & 31) == 0) red[tid >> 5] = ss;
    __syncthreads();
    float tot = 0.f;
    #pragma unroll
    for (int i = 0; i < 8; i++) tot += red[i];
    float inv = rsqrtf(tot * (1.0f / H_DIM) + 1e-6f);
    float4 ga = gr[tid], gb = gr[tid + 256];
    float4 oa, ob;
    oa.x = a.x*inv*ga.x; oa.y = a.y*inv*ga.y; oa.z = a.z*inv*ga.z; oa.w = a.w*inv*ga.w;
    ob.x = b.x*inv*gb.x; ob.y = b.y*inv*gb.y; ob.z = b.z*inv*gb.z; ob.w = b.w*inv*gb.w;
    size_t base = (size_t)row * H_DIM;
    if (F32) {
        reinterpret_cast<float4*>(of + base)[tid] = oa;
        reinterpret_cast<float4*>(of + base)[tid + 256] = ob;
    }
    size_t c0 = base + (size_t)tid * 4, c1 = base + (size_t)(tid + 256) * 4;
    wr2(ohi, olo, c0,     oa.x, oa.y);
    wr2(ohi, olo, c0 + 2, oa.z, oa.w);
    wr2(ohi, olo, c1,     ob.x, ob.y);
    wr2(ohi, olo, c1 + 2, ob.z, ob.w);
}

// ================= tensor-core GEMM (bf16 split, mma.sync m16n8k16) =======
__device__ __forceinline__ void cp16(uint32_t dst, const void* src, bool v)
{
    if (v) asm volatile("cp.async.cg.shared.global [%0], [%1], 16;\n" :: "r"(dst), "l"(src));
    else   asm volatile("st.shared.v4.b32 [%0], {%1,%1,%1,%1};\n" :: "r"(dst), "r"(0u));
}
#define CP_COMMIT() asm volatile("cp.async.commit_group;\n" ::)
#define CP_WAIT0()  asm volatile("cp.async.wait_group 0;\n" ::)
#define CP_WAIT1()  asm volatile("cp.async.wait_group 1;\n" ::)

#define MMA_BF16(d, a, b0_, b1_) \
    asm volatile("mma.sync.aligned.m16n8k16.row.col.f32.bf16.bf16.f32 " \
        "{%0,%1,%2,%3},{%4,%5,%6,%7},{%8,%9},{%0,%1,%2,%3};" \
        : "+f"(d[0]), "+f"(d[1]), "+f"(d[2]), "+f"(d[3]) \
        : "r"(a[0]), "r"(a[1]), "r"(a[2]), "r"(a[3]), "r"(b0_), "r"(b1_))

// MODE: 0 plain store, 1 +residual, 2 MoE-up (gather A rows via perm), 3 MoE-down (scaled scatter)
template<int MODE>
__global__ __launch_bounds__(256) void mma_gemm(
    const bf16* __restrict__ Ahi, const bf16* __restrict__ Alo,
    const bf16* __restrict__ Bhi, const bf16* __restrict__ Blo,
    float* __restrict__ C, const float* __restrict__ R,
    int M, int N, int K)
{
    int off = 0;
    if (MODE >= 2) {
        int e = blockIdx.z;
        M = g_cnt[e]; off = g_off[e];
        size_t w = (size_t)K * N;
        Bhi += (size_t)e * w; Blo += (size_t)e * w;
        if (MODE == 3) { Ahi += (size_t)off * K; Alo += (size_t)off * K; }
    }
    int bm = blockIdx.y * 128;
    if (bm >= M) return;
    int bn = blockIdx.x * 128;

    extern __shared__ char smch[];
    uint32_t smem = (uint32_t)__cvta_generic_to_shared(smch);

    int tid = threadIdx.x, lane = tid & 31, warp = tid >> 5;

    int ar0 = tid >> 2, ac = (tid & 3) << 3;
    int ar1 = ar0 + 64;
    int br0 = tid >> 4, bc = (tid & 15) << 3;
    int br1 = br0 + 16;
    bool av0 = (bm + ar0) < M, av1 = (bm + ar1) < M;
    long ra0, ra1;
    if (MODE == 2) {
        ra0 = av0 ? (long)(g_perm[off + bm + ar0] >> 1) * K : 0;
        ra1 = av1 ? (long)(g_perm[off + bm + ar1] >> 1) * K : 0;
    } else {
        ra0 = (long)(av0 ? bm + ar0 : 0) * K;
        ra1 = (long)(av1 ? bm + ar1 : 0) * K;
    }
    const bf16 *pa0h = Ahi + ra0 + ac, *pa1h = Ahi + ra1 + ac;
    const bf16 *pa0l = Alo + ra0 + ac, *pa1l = Alo + ra1 + ac;
    const bf16 *pb0h = Bhi + (size_t)br0 * N + bn + bc, *pb1h = Bhi + (size_t)br1 * N + bn + bc;
    const bf16 *pb0l = Blo + (size_t)br0 * N + bn + bc, *pb1l = Blo + (size_t)br1 * N + bn + bc;
    uint32_t sa0 = (uint32_t)(ar0 * 40 + ac) * 2, sa1 = (uint32_t)(ar1 * 40 + ac) * 2;
    uint32_t sb0 = (uint32_t)(br0 * 136 + bc) * 2, sb1 = (uint32_t)(br1 * 136 + bc) * 2;

    auto load_tile = [&](int stage, int kt) {
        uint32_t b = smem + stage * 37888;
        long ko = (long)kt * 32;
        long kb = ko * N;
        cp16(b + sa0,          pa0h + ko, av0);
        cp16(b + sa1,          pa1h + ko, av1);
        cp16(b + 10240 + sa0,  pa0l + ko, av0);
        cp16(b + 10240 + sa1,  pa1l + ko, av1);
        cp16(b + 20480 + sb0,  pb0h + kb, true);
        cp16(b + 20480 + sb1,  pb1h + kb, true);
        cp16(b + 29184 + sb0,  pb0l + kb, true);
        cp16(b + 29184 + sb1,  pb1l + kb, true);
        CP_COMMIT();
    };

    int m0 = (warp >> 2) * 64, n0 = (warp & 3) * 32;
    float acc[4][4][4] = {};

    uint32_t a_off = (uint32_t)((m0 + (lane & 15)) * 40 + ((lane >> 4) << 3)) * 2;
    uint32_t b_off = (uint32_t)((lane & 15) * 136 + n0) * 2;

    int nk = K >> 5;
    load_tile(0, 0);
    for (int kt = 0; kt < nk; ++kt) {
        int buf = kt & 1;
        if (kt + 1 < nk) {
            load_tile(buf ^ 1, kt + 1);
            CP_WAIT1();
        } else {
            CP_WAIT0();
        }
        __syncthreads();
        uint32_t sbase = smem + buf * 37888;
        #pragma unroll
        for (int kk = 0; kk < 2; ++kk) {
            uint32_t ah[4][4], al[4][4];
            #pragma unroll
            for (int i = 0; i < 4; ++i) {
                uint32_t addr = sbase + a_off + (uint32_t)(i * 640 + kk * 16) * 2;
                asm volatile("ldmatrix.sync.aligned.m8n8.x4.shared.b16 {%0,%1,%2,%3}, [%4];"
                    : "=r"(ah[i][0]), "=r"(ah[i][1]), "=r"(ah[i][2]), "=r"(ah[i][3]) : "r"(addr));
                asm volatile("ldmatrix.sync.aligned.m8n8.x4.shared.b16 {%0,%1,%2,%3}, [%4];"
                    : "=r"(al[i][0]), "=r"(al[i][1]), "=r"(al[i][2]), "=r"(al[i][3]) : "r"(addr + 10240));
            }
            #pragma unroll
            for (int j = 0; j < 4; ++j) {
                uint32_t baddr = sbase + 20480 + b_off + (uint32_t)(kk * 2176 + j * 8) * 2;
                uint32_t bh0, bh1, bl0, bl1;
                asm volatile("ldmatrix.sync.aligned.m8n8.x2.trans.shared.b16 {%0,%1}, [%2];"
                    : "=r"(bh0), "=r"(bh1) : "r"(baddr));
                asm volatile("ldmatrix.sync.aligned.m8n8.x2.trans.shared.b16 {%0,%1}, [%2];"
                    : "=r"(bl0), "=r"(bl1) : "r"(baddr + 8704));
                #pragma unroll
                for (int i = 0; i < 4; ++i) {
                    MMA_BF16(acc[i][j], ah[i], bh0, bh1);
                    MMA_BF16(acc[i][j], ah[i], bl0, bl1);
                    MMA_BF16(acc[i][j], al[i], bh0, bh1);
                }
            }
        }
        __syncthreads();
    }

    int tq = lane >> 2, tr = lane & 3;
    #pragma unroll
    for (int i = 0; i < 4; ++i) {
        #pragma unroll
        for (int h = 0; h < 2; ++h) {
            int row = bm + m0 + i * 16 + tq + h * 8;
            if (MODE >= 2 && row >= M) continue;
            size_t drow; float w = 1.f;
            if (MODE == 2)      drow = (size_t)(off + row);
            else if (MODE == 3) {
                int code = g_perm[off + row];
                w = g_topw[code];
                drow = (size_t)((code & 1) * T_DIM + (code >> 1));
            }
            else                drow = (size_t)row;
            float* cp = C + drow * N + bn + n0 + tr * 2;
            #pragma unroll
            for (int j = 0; j < 4; ++j) {
                float v0 = acc[i][j][h * 2], v1 = acc[i][j][h * 2 + 1];
                if (MODE == 1) {
                    const float* rp = R + (size_t)row * N + bn + n0 + tr * 2 + j * 8;
                    v0 += rp[0]; v1 += rp[1];
                }
                if (MODE == 3) { v0 *= w; v1 *= w; }
                *(float2*)(cp + j * 8) = make_float2(v0, v1);
            }
        }
    }
}

// ---------------- RoPE + convert to head-major bf16 planes ----------------
__global__ void rope_cvt_kernel()
{
    int idx = blockIdx.x * blockDim.x + threadIdx.x;
    if (idx >= T_DIM * NHEAD * 32) return;
    int i = idx & 31;
    int h = (idx >> 5) & 15;
    int t = idx >> 9;
    const float* base = g_qkv + (size_t)t * (3*H_DIM) + h * HD;
    size_t po = ((size_t)h * T_DIM + t) * HD;
    const float qs = 0.08838834764831845f;  // 1/sqrt(128)

    int d0 = 2 * i;
    float f0 = powf(10000.f, -(float)d0 * (1.f/64.f));
    float f1 = powf(10000.f, -(float)(d0+1) * (1.f/64.f));
    float s0, c0, s1, c1;
    sincosf((float)t * f0, &s0, &c0);
    sincosf((float)t * f1, &s1, &c1);

    {   // Q (pre-scaled)
        float a0 = base[d0], a1 = base[d0+1], b0 = base[d0+64], b1 = base[d0+65];
        wr2(g_q_hi, g_q_lo, po + d0,      (a0*c0 - b0*s0)*qs, (a1*c1 - b1*s1)*qs);
        wr2(g_q_hi, g_q_lo, po + d0 + 64, (a0*s0 + b0*c0)*qs, (a1*s1 + b1*c1)*qs);
    }
    {   // K
        const float* kb = base + H_DIM;
        float a0 = kb[d0], a1 = kb[d0+1], b0 = kb[d0+64], b1 = kb[d0+65];
        wr2(g_k_hi, g_k_lo, po + d0,      a0*c0 - b0*s0, a1*c1 - b1*s1);
        wr2(g_k_hi, g_k_lo, po + d0 + 64, a0*s0 + b0*c0, a1*s1 + b1*c1);
    }
    {   // V
        const float* vb = base + 2*H_DIM;
        int dv = 4 * i;
        wr2(g_v_hi, g_v_lo, po + dv,     vb[dv],   vb[dv+1]);
        wr2(g_v_hi, g_v_lo, po + dv + 2, vb[dv+2], vb[dv+3]);
    }
}

// ================= tensor-core causal flash attention =====================
// CTA: 128 q-rows, 8 warps x 16 rows. KV tiles: 64 keys, double buffered.
// Smem rows padded to 136 bf16 (272B). All mma m16n8k16 bf16, 3-term splits.
#define FLS_QL   34816                 // 128*136*2
#define FLS_ST0  69632                 // 2*34816
#define FLS_STG  69632                 // 4*64*136*2
#define FLS_KL   17408
#define FLS_VH   34816
#define FLS_VL   52224
#define FLS_SMEM (FLS_ST0 + 2*FLS_STG) // 208896

__global__ __launch_bounds__(256) void flash_tc_kernel()
{
    extern __shared__ __align__(1024) char smch[];
    uint32_t smem = (uint32_t)__cvta_generic_to_shared(smch);
    int head = blockIdx.y;
    int qb = gridDim.x - 1 - blockIdx.x;   // largest blocks launch first
    int bm = qb * 128;
    int tid = threadIdx.x, lane = tid & 31, warp = tid >> 5;
    int g = lane >> 2, t = lane & 3;

    size_t hb = (size_t)head * T_DIM * HD;
    const bf16 *Qh = g_q_hi + hb, *Ql = g_q_lo + hb;
    const bf16 *Kh = g_k_hi + hb, *Kl = g_k_lo + hb;
    const bf16 *Vh = g_v_hi + hb, *Vl = g_v_lo + hb;

    // load Q tile (128 rows x 128 elems, hi+lo)
    #pragma unroll
    for (int i = 0; i < 8; ++i) {
        int c = tid + i * 256;
        int r = c >> 4, col = (c & 15) * 8;
        uint32_t so = (uint32_t)(r * 136 + col) * 2;
        const bf16* gq = Qh + (size_t)(bm + r) * HD + col;
        cp16(smem + so,          gq, true);
        cp16(smem + FLS_QL + so, Ql + (size_t)(bm + r) * HD + col, true);
    }
    auto load_kv = [&](int st, int kt) {
        uint32_t b = smem + FLS_ST0 + st * FLS_STG;
        #pragma unroll
        for (int i = 0; i < 4; ++i) {
            int c = tid + i * 256;
            int r = c >> 4, col = (c & 15) * 8;
            size_t go = (size_t)(kt * 64 + r) * HD + col;
            uint32_t so = (uint32_t)(r * 136 + col) * 2;
            cp16(b + so,          Kh + go, true);
            cp16(b + FLS_KL + so, Kl + go, true);
            cp16(b + FLS_VH + so, Vh + go, true);
            cp16(b + FLS_VL + so, Vl + go, true);
        }
        CP_COMMIT();
    };
    load_kv(0, 0);   // commit covers Q + KV0

    int ntiles = (bm >> 6) + 2;
    float oacc[16][4];
    #pragma unroll
    for (int j = 0; j < 16; ++j) { oacc[j][0]=0; oacc[j][1]=0; oacc[j][2]=0; oacc[j][3]=0; }
    float m0 = -1e30f, m1 = -1e30f, l0 = 0.f, l1 = 0.f;

    for (int kt = 0; kt < ntiles; ++kt) {
        if (kt + 1 < ntiles) { load_kv((kt + 1) & 1, kt + 1); CP_WAIT1(); }
        else CP_WAIT0();
        __syncthreads();
        uint32_t stb = smem + FLS_ST0 + (kt & 1) * FLS_STG;

        // S = Q K^T (3-term)
        float sacc[8][4];
        #pragma unroll
        for (int j = 0; j < 8; ++j) { sacc[j][0]=0; sacc[j][1]=0; sacc[j][2]=0; sacc[j][3]=0; }
        #pragma unroll
        for (int ks = 0; ks < 8; ++ks) {
            uint32_t qh[4], ql[4];
            uint32_t qaddr = smem + (uint32_t)((warp*16 + (lane & 15)) * 136 + ks*16 + 8*(lane >> 4)) * 2;
            asm volatile("ldmatrix.sync.aligned.m8n8.x4.shared.b16 {%0,%1,%2,%3}, [%4];"
                : "=r"(qh[0]), "=r"(qh[1]), "=r"(qh[2]), "=r"(qh[3]) : "r"(qaddr));
            asm volatile("ldmatrix.sync.aligned.m8n8.x4.shared.b16 {%0,%1,%2,%3}, [%4];"
                : "=r"(ql[0]), "=r"(ql[1]), "=r"(ql[2]), "=r"(ql[3]) : "r"(qaddr + FLS_QL));
            #pragma unroll
            for (int j = 0; j < 8; ++j) {
                uint32_t kaddr = stb + (uint32_t)((j*8 + (lane & 7)) * 136 + ks*16 + 8*((lane >> 3) & 1)) * 2;
                uint32_t kh0, kh1, kl0, kl1;
                asm volatile("ldmatrix.sync.aligned.m8n8.x2.shared.b16 {%0,%1}, [%2];"
                    : "=r"(kh0), "=r"(kh1) : "r"(kaddr));
                asm volatile("ldmatrix.sync.aligned.m8n8.x2.shared.b16 {%0,%1}, [%2];"
                    : "=r"(kl0), "=r"(kl1) : "r"(kaddr + FLS_KL));
                MMA_BF16(sacc[j], qh, kh0, kh1);
                MMA_BF16(sacc[j], qh, kl0, kl1);
                MMA_BF16(sacc[j], ql, kh0, kh1);
            }
        }

        // causal mask (only relevant for last two tiles)
        if (kt >= (bm >> 6)) {
            int qr0 = bm + warp*16 + g, qr1 = qr0 + 8;
            #pragma unroll
            for (int j = 0; j < 8; ++j) {
                int key = kt*64 + j*8 + 2*t;
                if (key     > qr0) sacc[j][0] = -1e30f;
                if (key + 1 > qr0) sacc[j][1] = -1e30f;
                if (key     > qr1) sacc[j][2] = -1e30f;
                if (key + 1 > qr1) sacc[j][3] = -1e30f;
            }
        }

        // online softmax
        float mx0 = -1e30f, mx1 = -1e30f;
        #pragma unroll
        for (int j = 0; j < 8; ++j) {
            mx0 = fmaxf(mx0, fmaxf(sacc[j][0], sacc[j][1]));
            mx1 = fmaxf(mx1, fmaxf(sacc[j][2], sacc[j][3]));
        }
        mx0 = fmaxf(mx0, __shfl_xor_sync(0xffffffffu, mx0, 1));
        mx0 = fmaxf(mx0, __shfl_xor_sync(0xffffffffu, mx0, 2));
        mx1 = fmaxf(mx1, __shfl_xor_sync(0xffffffffu, mx1, 1));
        mx1 = fmaxf(mx1, __shfl_xor_sync(0xffffffffu, mx1, 2));
        float mn0 = fmaxf(m0, mx0), mn1 = fmaxf(m1, mx1);
        float al0 = __expf(m0 - mn0), al1 = __expf(m1 - mn1);
        m0 = mn0; m1 = mn1;
        float su0 = 0.f, su1 = 0.f;
        #pragma unroll
        for (int j = 0; j < 8; ++j) {
            float p0 = __expf(sacc[j][0] - mn0); sacc[j][0] = p0; su0 += p0;
            float p1 = __expf(sacc[j][1] - mn0); sacc[j][1] = p1; su0 += p1;
            float p2 = __expf(sacc[j][2] - mn1); sacc[j][2] = p2; su1 += p2;
            float p3 = __expf(sacc[j][3] - mn1); sacc[j][3] = p3; su1 += p3;
        }
        su0 += __shfl_xor_sync(0xffffffffu, su0, 1);
        su0 += __shfl_xor_sync(0xffffffffu, su0, 2);
        su1 += __shfl_xor_sync(0xffffffffu, su1, 1);
        su1 += __shfl_xor_sync(0xffffffffu, su1, 2);
        l0 = l0 * al0 + su0;
        l1 = l1 * al1 + su1;
        #pragma unroll
        for (int j = 0; j < 16; ++j) {
            oacc[j][0] *= al0; oacc[j][1] *= al0;
            oacc[j][2] *= al1; oacc[j][3] *= al1;
        }

        // O += P V (3-term; P repacked from S fragments)
        #pragma unroll
        for (int kk = 0; kk < 4; ++kk) {
            uint32_t ph[4], pl[4];
            split_pair(sacc[2*kk][0],   sacc[2*kk][1],   ph[0], pl[0]);
            split_pair(sacc[2*kk][2],   sacc[2*kk][3],   ph[1], pl[1]);
            split_pair(sacc[2*kk+1][0], sacc[2*kk+1][1], ph[2], pl[2]);
            split_pair(sacc[2*kk+1][2], sacc[2*kk+1][3], ph[3], pl[3]);
            #pragma unroll
            for (int j = 0; j < 16; ++j) {
                uint32_t vaddr = stb + FLS_VH + (uint32_t)((kk*16 + (lane & 15)) * 136 + j*8) * 2;
                uint32_t vh0, vh1, vl0, vl1;
                asm volatile("ldmatrix.sync.aligned.m8n8.x2.trans.shared.b16 {%0,%1}, [%2];"
                    : "=r"(vh0), "=r"(vh1) : "r"(vaddr));
                asm volatile("ldmatrix.sync.aligned.m8n8.x2.trans.shared.b16 {%0,%1}, [%2];"
                    : "=r"(vl0), "=r"(vl1) : "r"(vaddr + (FLS_VL - FLS_VH)));
                MMA_BF16(oacc[j], ph, vh0, vh1);
                MMA_BF16(oacc[j], ph, vl0, vl1);
                MMA_BF16(oacc[j], pl, vh0, vh1);
            }
        }
        __syncthreads();
    }

    // epilogue: normalize + write ctx hi/lo (token-major)
    float inv0 = 1.f / l0, inv1 = 1.f / l1;
    int r0 = bm + warp*16 + g, r1 = r0 + 8;
    size_t b0 = (size_t)r0 * H_DIM + head * HD;
    size_t b1 = (size_t)r1 * H_DIM + head * HD;
    #pragma unroll
    for (int j = 0; j < 16; ++j) {
        int col = j*8 + 2*t;
        wr2(g_ctx_hi, g_ctx_lo, b0 + col, oacc[j][0]*inv0, oacc[j][1]*inv0);
        wr2(g_ctx_hi, g_ctx_lo, b1 + col, oacc[j][2]*inv1, oacc[j][3]*inv1);
    }
}

// ---------------- router: logits + softmax-top2 (1 warp / token) --------
__global__ __launch_bounds__(256) void router_kernel(const float* __restrict__ gate_w)
{
    int gwarp = (blockIdx.x * blockDim.x + threadIdx.x) >> 5;
    int lane = threadIdx.x & 31;
    if (gwarp >= T_DIM) return;
    const float* hrow = g_h2f + (size_t)gwarp * H_DIM;
    float acc[NE];
    #pragma unroll
    for (int e = 0; e < NE; e++) acc[e] = 0.f;
    for (int i = lane; i < H_DIM; i += 32) {
        float hv = hrow[i];
        const float4* gw = reinterpret_cast<const float4*>(gate_w + (size_t)i * NE);
        #pragma unroll
        for (int q = 0; q < 4; q++) {
            float4 g4 = gw[q];
            acc[q*4+0] += hv * g4.x;
            acc[q*4+1] += hv * g4.y;
            acc[q*4+2] += hv * g4.z;
            acc[q*4+3] += hv * g4.w;
        }
    }
    #pragma unroll
    for (int e = 0; e < NE; e++)
        #pragma unroll
        for (int off = 16; off; off >>= 1)
            acc[e] += __shfl_xor_sync(0xffffffffu, acc[e], off);
    if (lane == 0) {
        float best = -1e30f; int bi = 0;
        #pragma unroll
        for (int e = 0; e < NE; e++) if (acc[e] > best) { best = acc[e]; bi = e; }
        float best2 = -1e30f; int bi2 = 0;
        #pragma unroll
        for (int e = 0; e < NE; e++) if (e != bi && acc[e] > best2) { best2 = acc[e]; bi2 = e; }
        float e1 = expf(best2 - best);
        float w0 = 1.f / (1.f + e1);
        float w1 = e1 / (1.f + e1);
        g_topi[2*gwarp]   = bi;  g_topw[2*gwarp]   = w0;
        g_topi[2*gwarp+1] = bi2; g_topw[2*gwarp+1] = w1;
    }
}

// ---------------- expert grouping ----------------
__global__ void zero_cnt_kernel() {
    int i = threadIdx.x;
    if (i < NE) { g_cnt[i] = 0; g_cur[i] = 0; }
}
__global__ void count_kernel() {
    int i = blockIdx.x * blockDim.x + threadIdx.x;
    if (i < TK) atomicAdd(&g_cnt[g_topi[i]], 1);
}
__global__ void scan_kernel() {
    if (threadIdx.x == 0) {
        int o = 0;
        for (int e = 0; e < NE; e++) { g_off[e] = o; g_cur[e] = o; o += g_cnt[e]; }
    }
}
__global__ void scatter_kernel() {
    int i = blockIdx.x * blockDim.x + threadIdx.x;
    if (i < TK) {
        int e = g_topi[i];
        int p = atomicAdd(&g_cur[e], 1);
        g_perm[p] = i;
    }
}

// ---------------- moe activation ----------------
__global__ void moe_act_kernel()
{
    long i = ((long)blockIdx.x * blockDim.x + threadIdx.x) * 2;
    if (i >= (long)TK * FF) return;
    long p = i >> 10;
    int  j = (int)(i & 1023);
    const float* gp = g_gu + p * (2*FF);
    float g0 = gp[j],        g1 = gp[j+1];
    float u0 = gp[FF + j],   u1 = gp[FF + j + 1];
    float a0 = g0 / (1.f + expf(-g0)) * u0;
    float a1 = g1 / (1.f + expf(-g1)) * u1;
    wr2(g_act_hi, g_act_lo, (size_t)i, a0, a1);
}

// ---------------- shared-FFN GLU ----------------
__global__ void glu_kernel()
{
    long i = ((long)blockIdx.x * blockDim.x + threadIdx.x) * 2;
    if (i >= (long)T_DIM * SF) return;
    long t = i >> 12;
    int  j = (int)(i & (SF - 1));
    const float* gp = g_sg + t * (2*SF);
    float g0 = gp[j],       g1 = gp[j+1];
    float u0 = gp[SF + j],  u1 = gp[SF + j + 1];
    float a0 = g0 / (1.f + expf(-g0)) * u0;
    float a1 = g1 / (1.f + expf(-g1)) * u1;
    wr2(g_mid_hi, g_mid_lo, (size_t)i, a0, a1);
}

// ---------------- final sum ----------------
__global__ void final_add_kernel(float* __restrict__ out)
{
    int i = blockIdx.x * blockDim.x + threadIdx.x;
    const float4* a  = reinterpret_cast<const float4*>(g_x1);
    const float4* s0 = reinterpret_cast<const float4*>(g_slot);
    const float4* s1 = reinterpret_cast<const float4*>(g_slot + (size_t)T_DIM * H_DIM);
    const float4* sh = reinterpret_cast<const float4*>(g_sho);
    float4 va = a[i], v0 = s0[i], v1 = s1[i], vs = sh[i];
    float4 r;
    r.x = va.x + v0.x + v1.x + vs.x;
    r.y = va.y + v0.y + v1.y + vs.y;
    r.z = va.z + v0.z + v1.z + vs.z;
    r.w = va.w + v0.w + v1.w + vs.w;
    reinterpret_cast<float4*>(out)[i] = r;
}

// ---------------- host launcher ----------------
#define GETSYM(p, s) cudaGetSymbolAddress((void**)&p, s)

extern "C" void kernel_launch(void* const* d_in, const int* in_sizes, int n_in,
                              void* d_out, int out_size)
{
    (void)in_sizes; (void)n_in; (void)out_size;
    const float* x       = (const float*)d_in[0];
    const float* gamma1  = (const float*)d_in[1];
    const float* gamma2  = (const float*)d_in[2];
    const float* w_qkv   = (const float*)d_in[3];
    const float* w_o     = (const float*)d_in[4];
    const float* gate_w  = (const float*)d_in[5];
    const float* moe_upw = (const float*)d_in[6];
    const float* moe_dnw = (const float*)d_in[7];
    const float* w13     = (const float*)d_in[8];
    const float* wdown   = (const float*)d_in[9];
    float* out = (float*)d_out;

    float *pqkv, *px1, *ph2f, *psg, *psho, *pgu, *pslot;
    GETSYM(pqkv, g_qkv); GETSYM(px1, g_x1); GETSYM(ph2f, g_h2f);
    GETSYM(psg, g_sg);   GETSYM(psho, g_sho); GETSYM(pgu, g_gu); GETSYM(pslot, g_slot);

    bf16 *h_hi,*h_lo,*ctx_hi,*ctx_lo,*h2_hi,*h2_lo,*mid_hi,*mid_lo,*act_hi,*act_lo;
    GETSYM(h_hi, g_h_hi);   GETSYM(h_lo, g_h_lo);
    GETSYM(ctx_hi, g_ctx_hi); GETSYM(ctx_lo, g_ctx_lo);
    GETSYM(h2_hi, g_h2_hi); GETSYM(h2_lo, g_h2_lo);
    GETSYM(mid_hi, g_mid_hi); GETSYM(mid_lo, g_mid_lo);
    GETSYM(act_hi, g_act_hi); GETSYM(act_lo, g_act_lo);

    bf16 *wq_hi,*wq_lo,*wo_hi,*wo_lo,*wu_hi,*wu_lo,*wd_hi,*wd_lo,*w13_hi,*w13_lo,*wd2_hi,*wd2_lo;
    GETSYM(wq_hi, w_qkv_hi); GETSYM(wq_lo, w_qkv_lo);
    GETSYM(wo_hi, w_o_hi);   GETSYM(wo_lo, w_o_lo);
    GETSYM(wu_hi, w_up_hi);  GETSYM(wu_lo, w_up_lo);
    GETSYM(wd_hi, w_dn_hi);  GETSYM(wd_lo, w_dn_lo);
    GETSYM(w13_hi, w_13_hi); GETSYM(w13_lo, w_13_lo);
    GETSYM(wd2_hi, w_d2_hi); GETSYM(wd2_lo, w_d2_lo);

    const int gemm_smem = 75776;
    cudaFuncSetAttribute(mma_gemm<0>, cudaFuncAttributeMaxDynamicSharedMemorySize, gemm_smem);
    cudaFuncSetAttribute(mma_gemm<1>, cudaFuncAttributeMaxDynamicSharedMemorySize, gemm_smem);
    cudaFuncSetAttribute(mma_gemm<2>, cudaFuncAttributeMaxDynamicSharedMemorySize, gemm_smem);
    cudaFuncSetAttribute(mma_gemm<3>, cudaFuncAttributeMaxDynamicSharedMemorySize, gemm_smem);
    cudaFuncSetAttribute(flash_tc_kernel, cudaFuncAttributeMaxDynamicSharedMemorySize, FLS_SMEM);

    // weight splits (hi/lo bf16 planes, [K][N] layout)
    auto cvt = [&](const float* src, bf16* hi, bf16* lo, long n) {
        long n4 = n / 4;
        cvt_kernel<<<(unsigned)((n4 + 255) / 256), 256>>>(src, hi, lo, n4);
    };
    cvt(w_qkv,   wq_hi,  wq_lo,  (long)H_DIM * 3 * H_DIM);
    cvt(w_o,     wo_hi,  wo_lo,  (long)H_DIM * H_DIM);
    cvt(moe_upw, wu_hi,  wu_lo,  (long)NE * H_DIM * 2 * FF);
    cvt(moe_dnw, wd_hi,  wd_lo,  (long)NE * FF * H_DIM);
    cvt(w13,     w13_hi, w13_lo, (long)H_DIM * 2 * SF);
    cvt(wdown,   wd2_hi, wd2_lo, (long)SF * H_DIM);

    // 1. h = rmsnorm(x, gamma1)
    rmsnorm_cvt_kernel<false><<<T_DIM, 256>>>(x, gamma1, nullptr, h_hi, h_lo);
    // 2. qkv = h @ w_qkv
    mma_gemm<0><<<dim3(3*H_DIM/128, T_DIM/128, 1), 256, gemm_smem>>>(
        h_hi, h_lo, wq_hi, wq_lo, pqkv, nullptr, T_DIM, 3*H_DIM, H_DIM);
    // 3. RoPE + convert q/k/v to head-major bf16 planes
    rope_cvt_kernel<<<(T_DIM*NHEAD*32 + 255)/256, 256>>>();
    // 4. tensor-core flash attention -> ctx planes
    flash_tc_kernel<<<dim3(T_DIM/128, NHEAD), 256, FLS_SMEM>>>();
    // 5. x1 = x + ctx @ w_o
    mma_gemm<1><<<dim3(H_DIM/128, T_DIM/128, 1), 256, gemm_smem>>>(
        ctx_hi, ctx_lo, wo_hi, wo_lo, px1, x, T_DIM, H_DIM, H_DIM);
    // 6. h2 = rmsnorm(x1, gamma2)
    rmsnorm_cvt_kernel<true><<<T_DIM, 256>>>(px1, gamma2, ph2f, h2_hi, h2_lo);
    // 7. router
    router_kernel<<<T_DIM/8, 256>>>(gate_w);
    // 8-11. expert grouping
    zero_cnt_kernel<<<1, 32>>>();
    count_kernel<<<(TK + 255)/256, 256>>>();
    scan_kernel<<<1, 32>>>();
    scatter_kernel<<<(TK + 255)/256, 256>>>();
    // 12. moe up
    mma_gemm<2><<<dim3(2*FF/128, TK/128, NE), 256, gemm_smem>>>(
        h2_hi, h2_lo, wu_hi, wu_lo, pgu, nullptr, TK, 2*FF, H_DIM);
    // 13. moe activation
    moe_act_kernel<<<(unsigned)(((long)TK*FF/2 + 255)/256), 256>>>();
    // 14. moe down
    mma_gemm<3><<<dim3(H_DIM/128, TK/128, NE), 256, gemm_smem>>>(
        act_hi, act_lo, wd_hi, wd_lo, pslot, nullptr, TK, H_DIM, FF);
    // 15. shared ffn up
    mma_gemm<0><<<dim3(2*SF/128, T_DIM/128, 1), 256, gemm_smem>>>(
        h2_hi, h2_lo, w13_hi, w13_lo, psg, nullptr, T_DIM, 2*SF, H_DIM);
    // 16. shared glu
    glu_kernel<<<(unsigned)(((long)T_DIM*SF/2 + 255)/256), 256>>>();
    // 17. shared ffn down
    mma_gemm<0><<<dim3(H_DIM/128, T_DIM/128, 1), 256, gemm_smem>>>(
        mid_hi, mid_lo, wd2_hi, wd2_lo, psho, nullptr, T_DIM, H_DIM, SF);
    // 18. final sum
    final_add_kernel<<<(T_DIM*H_DIM/4 + 255)/256, 256>>>(out);
}